// round 16
// baseline (speedup 1.0000x reference)
#include <cuda_runtime.h>
#include <cuda_fp16.h>
#include <math.h>
#include <cstdint>

#define TT 2048      // tokens = B*S
#define EE 8         // experts
#define HH 768       // hidden
#define FF 3072      // ffn hidden
#define NSLOT (TT*2)
#define NSP2 3       // split-K for GEMM2 (576 active CTAs = ~2 full waves)

// ---------------- scratch (__device__ globals: allocation-free rule) --------
__device__ __half g_hmid[(size_t)NSLOT * FF];      // 25 MB (fp16 mid acts)
__device__ __half g_xh [(size_t)TT * HH];          // 3 MB  (fp16 x)
__device__ __half g_w1h[(size_t)EE * FF * HH];     // 37.7 MB (fp16 w1)
__device__ __half g_w2h[(size_t)EE * HH * FF];     // 37.7 MB (fp16 w2)
__device__ __half g_y  [(size_t)NSP2 * NSLOT * HH];// 18.9 MB (fp16 partials)
__device__ int    g_cnt[EE];
__device__ int    g_list[EE * TT];
__device__ float  g_slot_w[NSLOT];
__device__ int    g_slot_e[NSLOT];

// ---------------- helpers ----------------------------------------------------
__device__ __forceinline__ uint32_t smem_u32(const void* p) {
    uint32_t a;
    asm("{ .reg .u64 t; cvta.to.shared.u64 t, %1; cvt.u32.u64 %0, t; }" : "=r"(a) : "l"(p));
    return a;
}
__device__ __forceinline__ void cpa16(uint32_t dst, const void* src) {
    asm volatile("cp.async.cg.shared.global [%0], [%1], 16;\n" :: "r"(dst), "l"(src));
}
__device__ __forceinline__ void cpa_commit() { asm volatile("cp.async.commit_group;\n" ::: "memory"); }
__device__ __forceinline__ void cpa_wait1()  { asm volatile("cp.async.wait_group 1;\n" ::: "memory"); }

__device__ __forceinline__ void ldsm4(uint32_t r[4], uint32_t addr) {
    asm volatile("ldmatrix.sync.aligned.m8n8.x4.shared.b16 {%0,%1,%2,%3}, [%4];"
                 : "=r"(r[0]), "=r"(r[1]), "=r"(r[2]), "=r"(r[3]) : "r"(addr));
}
__device__ __forceinline__ void mma16(float c[4], const uint32_t a[4],
                                      uint32_t b0, uint32_t b1) {
    asm volatile(
        "mma.sync.aligned.m16n8k16.row.col.f32.f16.f16.f32 "
        "{%0,%1,%2,%3}, {%4,%5,%6,%7}, {%8,%9}, {%0,%1,%2,%3};"
        : "+f"(c[0]), "+f"(c[1]), "+f"(c[2]), "+f"(c[3])
        : "r"(a[0]), "r"(a[1]), "r"(a[2]), "r"(a[3]), "r"(b0), "r"(b1));
}

// ---------------- init / convert ---------------------------------------------
__global__ void init_kernel() {
    int i = threadIdx.x;
    if (i < EE) g_cnt[i] = 0;
}

// fp32 -> fp16 streaming convert: each thread converts 8 floats per step.
__global__ void cvt_half_kernel(const float4* __restrict__ src,
                                uint4* __restrict__ dst, int n8) {
    int i = blockIdx.x * blockDim.x + threadIdx.x;
    int stride = gridDim.x * blockDim.x;
    for (; i < n8; i += stride) {
        float4 v0 = src[2 * i], v1 = src[2 * i + 1];
        __half2 h0 = __floats2half2_rn(v0.x, v0.y);
        __half2 h1 = __floats2half2_rn(v0.z, v0.w);
        __half2 h2 = __floats2half2_rn(v1.x, v1.y);
        __half2 h3 = __floats2half2_rn(v1.z, v1.w);
        uint4 o;
        o.x = *(uint32_t*)&h0; o.y = *(uint32_t*)&h1;
        o.z = *(uint32_t*)&h2; o.w = *(uint32_t*)&h3;
        dst[i] = o;
    }
}

// Router: vectorized float4 loads; logits/top-2/softmax in fp32; writes fp16 x.
__global__ void router_kernel(const float* __restrict__ x,
                              const float* __restrict__ rw) {
    int gw   = (blockIdx.x * blockDim.x + threadIdx.x) >> 5;
    int lane = threadIdx.x & 31;
    if (gw >= TT) return;
    const float4* xt = (const float4*)(x + (size_t)gw * HH);
    float4 xv[6];
#pragma unroll
    for (int i = 0; i < 6; i++) xv[i] = xt[lane + 32 * i];
    uint2* xc = (uint2*)(g_xh + (size_t)gw * HH);
#pragma unroll
    for (int i = 0; i < 6; i++) {
        __half2 lo = __floats2half2_rn(xv[i].x, xv[i].y);
        __half2 hi = __floats2half2_rn(xv[i].z, xv[i].w);
        uint2 o; o.x = *(uint32_t*)&lo; o.y = *(uint32_t*)&hi;
        xc[lane + 32 * i] = o;
    }
    float lg[EE];
#pragma unroll
    for (int e = 0; e < EE; e++) {
        const float4* w = (const float4*)(rw + (size_t)e * HH);
        float s = 0.0f;
#pragma unroll
        for (int i = 0; i < 6; i++) {
            float4 wv = w[lane + 32 * i];
            s = fmaf(xv[i].x, wv.x, s); s = fmaf(xv[i].y, wv.y, s);
            s = fmaf(xv[i].z, wv.z, s); s = fmaf(xv[i].w, wv.w, s);
        }
#pragma unroll
        for (int o = 16; o; o >>= 1) s += __shfl_xor_sync(0xffffffffu, s, o);
        lg[e] = s;
    }
    if (lane == 0) {
        int i0 = 0;
#pragma unroll
        for (int e = 1; e < EE; e++) if (lg[e] > lg[i0]) i0 = e;
        int i1 = (i0 == 0) ? 1 : 0;
#pragma unroll
        for (int e = 0; e < EE; e++) {
            if (e == i0 || e == i1) continue;
            if (lg[e] > lg[i1]) i1 = e;
        }
        float ex = expf(lg[i1] - lg[i0]);
        float inv = 1.0f / (1.0f + ex);
        g_slot_w[gw * 2]     = inv;
        g_slot_w[gw * 2 + 1] = ex * inv;
        g_slot_e[gw * 2]     = i0;
        g_slot_e[gw * 2 + 1] = i1;
        int p = atomicAdd(&g_cnt[i0], 1); g_list[i0 * TT + p] = gw * 2;
        int q = atomicAdd(&g_cnt[i1], 1); g_list[i1 * TT + q] = gw * 2 + 1;
    }
}

// Combine: out[t] = w0*(Σ_s y[s][2t]+b2[e0]) + w1*(Σ_s y[s][2t+1]+b2[e1])
__global__ void combine_kernel(const float* __restrict__ b2,
                               float* __restrict__ out) {
    int idx = blockIdx.x * blockDim.x + threadIdx.x;   // one float4 per thread
    const int C4 = HH / 4;
    if (idx >= TT * C4) return;
    int t = idx / C4, c4 = idx % C4;
    const uint2* y = (const uint2*)g_y;                // 4 halves per uint2
    size_t r0  = (size_t)(2 * t) * C4 + c4;
    size_t r1  = r0 + C4;
    size_t off = (size_t)NSLOT * C4;                   // split stride
    float s0[4] = {0, 0, 0, 0}, s1[4] = {0, 0, 0, 0};
#pragma unroll
    for (int s = 0; s < NSP2; s++) {
        uint2 pa = y[s * off + r0], pb = y[s * off + r1];
        float2 a0 = __half22float2(*(__half2*)&pa.x);
        float2 a1 = __half22float2(*(__half2*)&pa.y);
        float2 b0 = __half22float2(*(__half2*)&pb.x);
        float2 b1 = __half22float2(*(__half2*)&pb.y);
        s0[0] += a0.x; s0[1] += a0.y; s0[2] += a1.x; s0[3] += a1.y;
        s1[0] += b0.x; s1[1] += b0.y; s1[2] += b1.x; s1[3] += b1.y;
    }
    int e0 = g_slot_e[2 * t], e1 = g_slot_e[2 * t + 1];
    float4 be0 = ((const float4*)b2)[(size_t)e0 * C4 + c4];
    float4 be1 = ((const float4*)b2)[(size_t)e1 * C4 + c4];
    float w0 = g_slot_w[2 * t], w1 = g_slot_w[2 * t + 1];
    float4 r;
    r.x = w0 * (s0[0] + be0.x) + w1 * (s1[0] + be1.x);
    r.y = w0 * (s0[1] + be0.y) + w1 * (s1[1] + be1.y);
    r.z = w0 * (s0[2] + be0.z) + w1 * (s1[2] + be1.z);
    r.w = w0 * (s0[3] + be0.w) + w1 * (s1[3] + be1.w);
    ((float4*)out)[idx] = r;
}

// ---------------- mma.sync fp16 grouped GEMM (R11 monolithic, frozen) --------
// CTA tile 128x128, BK=64 halves, 8 warps (4m x 2n), 3-stage cp.async,
// 2 CTAs/SM. fp32 accumulate.
// MODE 0: A = g_xh[token],  W = g_w1h[e] -> bias + GELU -> fp16 -> g_hmid[slot]
// MODE 1: A = g_hmid[slot], W = g_w2h[e] -> fp16 partials to g_y[split][slot]
template <int MODE, int KD, int ND, int NSPLIT>
__global__ __launch_bounds__(256, 2) void moe_gemm(
    const __half* __restrict__ W,
    const float* __restrict__ bias) {
    constexpr int BM = 128, BN = 128, BK = 64;
    constexpr int KSP = KD / NSPLIT;
    constexpr int NSLAB = KSP / BK;
    constexpr int STAGE = (BM + BN) * 128;      // 32 KB (128 B per row)

    extern __shared__ char dsm[];
    __shared__ int s_slot[BM];

    int e = blockIdx.z / NSPLIT, split = blockIdx.z % NSPLIT;
    int cnt = g_cnt[e];
    int m0 = blockIdx.y * BM;
    if (m0 >= cnt) return;
    int n0 = blockIdx.x * BN;
    int kbase = split * KSP;
    int tid = threadIdx.x, lane = tid & 31, wid = tid >> 5;
    int wm = (wid & 3) * 32, wn = (wid >> 2) * 64;

    const __half* __restrict__ Ap = (MODE == 0) ? g_xh : g_hmid;
    const __half* __restrict__ Wb = W + (size_t)e * ND * KD;

    for (int i = tid; i < BM; i += 256) {
        int r = m0 + i;
        s_slot[i] = g_list[e * TT + (r < cnt ? r : cnt - 1)];
    }
    __syncthreads();

    uint32_t sb = (smem_u32(dsm) + 127u) & ~127u;

    auto fill = [&](int st, int s) {
        int k0 = kbase + s * BK;
        uint32_t as = sb + st * STAGE;
        uint32_t bs = as + BM * 128;
#pragma unroll
        for (int j = 0; j < 4; j++) {            // A: 128 rows x 8 x 16B
            int idx = tid + j * 256;
            int r = idx >> 3, c = idx & 7;
            size_t arow = (MODE == 0) ? (size_t)(s_slot[r] >> 1) : (size_t)s_slot[r];
            cpa16(as + r * 128 + ((c * 16) ^ ((r & 7) << 4)),
                  Ap + arow * KD + k0 + c * 8);
        }
#pragma unroll
        for (int j = 0; j < 4; j++) {            // B: 128 rows x 8 x 16B
            int idx = tid + j * 256;
            int r = idx >> 3, c = idx & 7;
            cpa16(bs + r * 128 + ((c * 16) ^ ((r & 7) << 4)),
                  Wb + (size_t)(n0 + r) * KD + k0 + c * 8);
        }
    };

    fill(0, 0); cpa_commit();
    fill(1, 1); cpa_commit();

    float acc[2][8][4];
#pragma unroll
    for (int mt = 0; mt < 2; mt++)
#pragma unroll
        for (int nt = 0; nt < 8; nt++)
#pragma unroll
            for (int q = 0; q < 4; q++) acc[mt][nt][q] = 0.0f;

    int a_row = lane & 15;            // row within m16 tile
    int a_kx  = (lane >> 4) << 4;     // 0 or 16 bytes (k8 halves)
    int b_row = lane & 7;             // row within n8 tile
    int b_kx  = (lane >> 3) << 4;     // 0,16,32,48 bytes (4 k8 tiles)

    for (int s = 0; s < NSLAB; s++) {
        cpa_wait1();
        __syncthreads();
        if (s + 2 < NSLAB) fill((s + 2) % 3, s + 2);
        cpa_commit();

        uint32_t ab = sb + (s % 3) * STAGE;
        uint32_t bb = ab + BM * 128;
#pragma unroll
        for (int kh = 0; kh < 2; kh++) {          // k32-halves of the slab
            uint32_t b[8][4];
#pragma unroll
            for (int nt = 0; nt < 8; nt++) {
                int row = wn + nt * 8 + b_row;
                int kb  = kh * 64 + b_kx;
                ldsm4(b[nt], bb + row * 128 + (kb ^ ((row & 7) << 4)));
            }
#pragma unroll
            for (int ks = 0; ks < 2; ks++) {      // k16 steps within the half
                uint32_t a[2][4];
#pragma unroll
                for (int mt = 0; mt < 2; mt++) {
                    int row = wm + mt * 16 + a_row;
                    int kb  = kh * 64 + ks * 32 + a_kx;
                    ldsm4(a[mt], ab + row * 128 + (kb ^ ((row & 7) << 4)));
                }
#pragma unroll
                for (int mt = 0; mt < 2; mt++)
#pragma unroll
                    for (int nt = 0; nt < 8; nt++)
                        mma16(acc[mt][nt], a[mt], b[nt][ks * 2], b[nt][ks * 2 + 1]);
            }
        }
    }

    // ---------------- epilogue ----------------
    int g = lane >> 2, tig = lane & 3;
#pragma unroll
    for (int mt = 0; mt < 2; mt++) {
#pragma unroll
        for (int half = 0; half < 2; half++) {
            int rl = wm + mt * 16 + g + half * 8;
            if (m0 + rl >= cnt) continue;
            int slot = s_slot[rl];
            if (MODE == 0) {
                __half* dst = g_hmid + (size_t)slot * ND;
                const float* bp = bias + (size_t)e * ND;
#pragma unroll
                for (int nt = 0; nt < 8; nt++) {
                    int col = n0 + wn + nt * 8 + 2 * tig;
                    float v0 = acc[mt][nt][half * 2 + 0] + bp[col];
                    float v1 = acc[mt][nt][half * 2 + 1] + bp[col + 1];
                    v0 = 0.5f * v0 * (1.0f + erff(v0 * 0.70710678118654752f));
                    v1 = 0.5f * v1 * (1.0f + erff(v1 * 0.70710678118654752f));
                    *(__half2*)(dst + col) = __floats2half2_rn(v0, v1);
                }
            } else {
                __half* dst = g_y + ((size_t)split * NSLOT + slot) * ND;
#pragma unroll
                for (int nt = 0; nt < 8; nt++) {
                    int col = n0 + wn + nt * 8 + 2 * tig;
                    *(__half2*)(dst + col) = __floats2half2_rn(
                        acc[mt][nt][half * 2 + 0], acc[mt][nt][half * 2 + 1]);
                }
            }
        }
    }
}

// ---------------- launcher ---------------------------------------------------
extern "C" void kernel_launch(void* const* d_in, const int* in_sizes, int n_in,
                              void* d_out, int out_size) {
    const float* x  = (const float*)d_in[0];
    const float* rw = (const float*)d_in[1];
    const float* w1 = (const float*)d_in[2];
    const float* b1 = (const float*)d_in[3];
    const float* w2 = (const float*)d_in[4];
    const float* b2 = (const float*)d_in[5];
    float* out = (float*)d_out;

    void *p_w1h, *p_w2h;
    cudaGetSymbolAddress(&p_w1h, g_w1h);
    cudaGetSymbolAddress(&p_w2h, g_w2h);

    // Two side streams (proven safe); cvts serialized: w1 first, w2 under GEMM1.
    static cudaStream_t s_a = nullptr, s_b = nullptr;
    static cudaEvent_t ev_root = nullptr, ev_w1 = nullptr, ev_w2 = nullptr;
    if (s_a == nullptr) {
        cudaStreamCreateWithFlags(&s_a, cudaStreamNonBlocking);
        cudaStreamCreateWithFlags(&s_b, cudaStreamNonBlocking);
        cudaEventCreateWithFlags(&ev_root, cudaEventDisableTiming);
        cudaEventCreateWithFlags(&ev_w1,   cudaEventDisableTiming);
        cudaEventCreateWithFlags(&ev_w2,   cudaEventDisableTiming);
    }

    const int SMEM = 3 * 32768 + 128;
    cudaFuncSetAttribute(moe_gemm<0, HH, FF, 1>,
                         cudaFuncAttributeMaxDynamicSharedMemorySize, SMEM);
    cudaFuncSetAttribute(moe_gemm<1, FF, HH, NSP2>,
                         cudaFuncAttributeMaxDynamicSharedMemorySize, SMEM);

    // Fork: cvt_w1 alone at full bandwidth on s_a; cvt_w2 chained after it on
    // s_b so it overlaps GEMM1 (tensor-bound, low DRAM) instead of cvt_w1.
    cudaEventRecord(ev_root, 0);
    cudaStreamWaitEvent(s_a, ev_root, 0);
    cvt_half_kernel<<<4736, 256, 0, s_a>>>((const float4*)w1, (uint4*)p_w1h,
                                           EE * FF * HH / 8);
    cudaEventRecord(ev_w1, s_a);
    cudaStreamWaitEvent(s_b, ev_w1, 0);
    cvt_half_kernel<<<4736, 256, 0, s_b>>>((const float4*)w2, (uint4*)p_w2h,
                                           EE * HH * FF / 8);
    cudaEventRecord(ev_w2, s_b);

    // Main stream: init + router overlap cvt_w1.
    init_kernel<<<1, 32>>>();
    router_kernel<<<(TT * 32) / 256, 256>>>(x, rw);

    // GEMM1 (monolithic) after router + cvt_w1; cvt_w2 runs underneath it.
    cudaStreamWaitEvent(0, ev_w1, 0);
    dim3 g1(FF / 128, TT / 128, EE);
    moe_gemm<0, HH, FF, 1><<<g1, 256, SMEM>>>((const __half*)p_w1h, b1);

    // GEMM2 (monolithic, split-K=3) after GEMM1 + cvt_w2; fp16 partials.
    cudaStreamWaitEvent(0, ev_w2, 0);
    dim3 g2(HH / 128, TT / 128, EE * NSP2);
    moe_gemm<1, FF, HH, NSP2><<<g2, 256, SMEM>>>((const __half*)p_w2h, b2);

    // Combine split-K partials + bias + routing weights into out.
    combine_kernel<<<(TT * HH / 4 + 255) / 256, 256>>>(b2, out);
}

// round 17
// speedup vs baseline: 1.0647x; 1.0647x over previous
#include <cuda_runtime.h>
#include <cuda_fp16.h>
#include <math.h>
#include <cstdint>

#define TT 2048      // tokens = B*S
#define EE 8         // experts
#define HH 768       // hidden
#define FF 3072      // ffn hidden
#define NSLOT (TT*2)
#define NSP2 2       // split-K for GEMM2

// ---------------- scratch (__device__ globals: allocation-free rule) --------
__device__ __half g_hmid[(size_t)NSLOT * FF];      // 25 MB (fp16 mid acts)
__device__ __half g_xh [(size_t)TT * HH];          // 3 MB  (fp16 x)
__device__ __half g_w1h[(size_t)EE * FF * HH];     // 37.7 MB (fp16 w1)
__device__ __half g_w2h[(size_t)EE * HH * FF];     // 37.7 MB (fp16 w2)
__device__ __half g_y  [(size_t)NSP2 * NSLOT * HH];// 12.6 MB (fp16 partials)
__device__ int    g_cnt[EE];
__device__ int    g_list[EE * TT];
__device__ float  g_slot_w[NSLOT];
__device__ int    g_slot_e[NSLOT];

// ---------------- helpers ----------------------------------------------------
__device__ __forceinline__ uint32_t smem_u32(const void* p) {
    uint32_t a;
    asm("{ .reg .u64 t; cvta.to.shared.u64 t, %1; cvt.u32.u64 %0, t; }" : "=r"(a) : "l"(p));
    return a;
}
__device__ __forceinline__ void cpa16(uint32_t dst, const void* src) {
    asm volatile("cp.async.cg.shared.global [%0], [%1], 16;\n" :: "r"(dst), "l"(src));
}
__device__ __forceinline__ void cpa_commit() { asm volatile("cp.async.commit_group;\n" ::: "memory"); }
__device__ __forceinline__ void cpa_wait1()  { asm volatile("cp.async.wait_group 1;\n" ::: "memory"); }

__device__ __forceinline__ void ldsm4(uint32_t r[4], uint32_t addr) {
    asm volatile("ldmatrix.sync.aligned.m8n8.x4.shared.b16 {%0,%1,%2,%3}, [%4];"
                 : "=r"(r[0]), "=r"(r[1]), "=r"(r[2]), "=r"(r[3]) : "r"(addr));
}
__device__ __forceinline__ void mma16(float c[4], const uint32_t a[4],
                                      uint32_t b0, uint32_t b1) {
    asm volatile(
        "mma.sync.aligned.m16n8k16.row.col.f32.f16.f16.f32 "
        "{%0,%1,%2,%3}, {%4,%5,%6,%7}, {%8,%9}, {%0,%1,%2,%3};"
        : "+f"(c[0]), "+f"(c[1]), "+f"(c[2]), "+f"(c[3])
        : "r"(a[0]), "r"(a[1]), "r"(a[2]), "r"(a[3]), "r"(b0), "r"(b1));
}

// ---------------- init / convert ---------------------------------------------
__global__ void init_kernel() {
    int i = threadIdx.x;
    if (i < EE) g_cnt[i] = 0;
}

// fp32 -> fp16 streaming convert: each thread converts 8 floats per step.
__global__ void cvt_half_kernel(const float4* __restrict__ src,
                                uint4* __restrict__ dst, int n8) {
    int i = blockIdx.x * blockDim.x + threadIdx.x;
    int stride = gridDim.x * blockDim.x;
    for (; i < n8; i += stride) {
        float4 v0 = src[2 * i], v1 = src[2 * i + 1];
        __half2 h0 = __floats2half2_rn(v0.x, v0.y);
        __half2 h1 = __floats2half2_rn(v0.z, v0.w);
        __half2 h2 = __floats2half2_rn(v1.x, v1.y);
        __half2 h3 = __floats2half2_rn(v1.z, v1.w);
        uint4 o;
        o.x = *(uint32_t*)&h0; o.y = *(uint32_t*)&h1;
        o.z = *(uint32_t*)&h2; o.w = *(uint32_t*)&h3;
        dst[i] = o;
    }
}

// Router: vectorized float4 loads; logits/top-2/softmax in fp32; writes fp16 x.
__global__ void router_kernel(const float* __restrict__ x,
                              const float* __restrict__ rw) {
    int gw   = (blockIdx.x * blockDim.x + threadIdx.x) >> 5;
    int lane = threadIdx.x & 31;
    if (gw >= TT) return;
    const float4* xt = (const float4*)(x + (size_t)gw * HH);
    float4 xv[6];
#pragma unroll
    for (int i = 0; i < 6; i++) xv[i] = xt[lane + 32 * i];
    uint2* xc = (uint2*)(g_xh + (size_t)gw * HH);
#pragma unroll
    for (int i = 0; i < 6; i++) {
        __half2 lo = __floats2half2_rn(xv[i].x, xv[i].y);
        __half2 hi = __floats2half2_rn(xv[i].z, xv[i].w);
        uint2 o; o.x = *(uint32_t*)&lo; o.y = *(uint32_t*)&hi;
        xc[lane + 32 * i] = o;
    }
    float lg[EE];
#pragma unroll
    for (int e = 0; e < EE; e++) {
        const float4* w = (const float4*)(rw + (size_t)e * HH);
        float s = 0.0f;
#pragma unroll
        for (int i = 0; i < 6; i++) {
            float4 wv = w[lane + 32 * i];
            s = fmaf(xv[i].x, wv.x, s); s = fmaf(xv[i].y, wv.y, s);
            s = fmaf(xv[i].z, wv.z, s); s = fmaf(xv[i].w, wv.w, s);
        }
#pragma unroll
        for (int o = 16; o; o >>= 1) s += __shfl_xor_sync(0xffffffffu, s, o);
        lg[e] = s;
    }
    if (lane == 0) {
        int i0 = 0;
#pragma unroll
        for (int e = 1; e < EE; e++) if (lg[e] > lg[i0]) i0 = e;
        int i1 = (i0 == 0) ? 1 : 0;
#pragma unroll
        for (int e = 0; e < EE; e++) {
            if (e == i0 || e == i1) continue;
            if (lg[e] > lg[i1]) i1 = e;
        }
        float ex = expf(lg[i1] - lg[i0]);
        float inv = 1.0f / (1.0f + ex);
        g_slot_w[gw * 2]     = inv;
        g_slot_w[gw * 2 + 1] = ex * inv;
        g_slot_e[gw * 2]     = i0;
        g_slot_e[gw * 2 + 1] = i1;
        int p = atomicAdd(&g_cnt[i0], 1); g_list[i0 * TT + p] = gw * 2;
        int q = atomicAdd(&g_cnt[i1], 1); g_list[i1 * TT + q] = gw * 2 + 1;
    }
}

// Combine: out[t] = w0*(Σ_s y[s][2t]+b2[e0]) + w1*(Σ_s y[s][2t+1]+b2[e1])
__global__ void combine_kernel(const float* __restrict__ b2,
                               float* __restrict__ out) {
    int idx = blockIdx.x * blockDim.x + threadIdx.x;   // one float4 per thread
    const int C4 = HH / 4;
    if (idx >= TT * C4) return;
    int t = idx / C4, c4 = idx % C4;
    const uint2* y = (const uint2*)g_y;                // 4 halves per uint2
    size_t r0  = (size_t)(2 * t) * C4 + c4;
    size_t r1  = r0 + C4;
    size_t off = (size_t)NSLOT * C4;                   // split stride
    float s0[4] = {0, 0, 0, 0}, s1[4] = {0, 0, 0, 0};
#pragma unroll
    for (int s = 0; s < NSP2; s++) {
        uint2 pa = y[s * off + r0], pb = y[s * off + r1];
        float2 a0 = __half22float2(*(__half2*)&pa.x);
        float2 a1 = __half22float2(*(__half2*)&pa.y);
        float2 b0 = __half22float2(*(__half2*)&pb.x);
        float2 b1 = __half22float2(*(__half2*)&pb.y);
        s0[0] += a0.x; s0[1] += a0.y; s0[2] += a1.x; s0[3] += a1.y;
        s1[0] += b0.x; s1[1] += b0.y; s1[2] += b1.x; s1[3] += b1.y;
    }
    int e0 = g_slot_e[2 * t], e1 = g_slot_e[2 * t + 1];
    float4 be0 = ((const float4*)b2)[(size_t)e0 * C4 + c4];
    float4 be1 = ((const float4*)b2)[(size_t)e1 * C4 + c4];
    float w0 = g_slot_w[2 * t], w1 = g_slot_w[2 * t + 1];
    float4 r;
    r.x = w0 * (s0[0] + be0.x) + w1 * (s1[0] + be1.x);
    r.y = w0 * (s0[1] + be0.y) + w1 * (s1[1] + be1.y);
    r.z = w0 * (s0[2] + be0.z) + w1 * (s1[2] + be1.z);
    r.w = w0 * (s0[3] + be0.w) + w1 * (s1[3] + be1.w);
    ((float4*)out)[idx] = r;
}

// ---------------- mma.sync fp16 grouped GEMM (R11 monolithic, frozen) --------
// CTA tile 128x128, BK=64 halves, 8 warps (4m x 2n), 3-stage cp.async,
// 2 CTAs/SM. fp32 accumulate.
// MODE 0: A = g_xh[token],  W = g_w1h[e] -> bias + GELU -> fp16 -> g_hmid[slot]
// MODE 1: A = g_hmid[slot], W = g_w2h[e] -> fp16 partials to g_y[split][slot]
template <int MODE, int KD, int ND, int NSPLIT>
__global__ __launch_bounds__(256, 2) void moe_gemm(
    const __half* __restrict__ W,
    const float* __restrict__ bias) {
    constexpr int BM = 128, BN = 128, BK = 64;
    constexpr int KSP = KD / NSPLIT;
    constexpr int NSLAB = KSP / BK;
    constexpr int STAGE = (BM + BN) * 128;      // 32 KB (128 B per row)

    extern __shared__ char dsm[];
    __shared__ int s_slot[BM];

    int e = blockIdx.z / NSPLIT, split = blockIdx.z % NSPLIT;
    int cnt = g_cnt[e];
    int m0 = blockIdx.y * BM;
    if (m0 >= cnt) return;
    int n0 = blockIdx.x * BN;
    int kbase = split * KSP;
    int tid = threadIdx.x, lane = tid & 31, wid = tid >> 5;
    int wm = (wid & 3) * 32, wn = (wid >> 2) * 64;

    const __half* __restrict__ Ap = (MODE == 0) ? g_xh : g_hmid;
    const __half* __restrict__ Wb = W + (size_t)e * ND * KD;

    for (int i = tid; i < BM; i += 256) {
        int r = m0 + i;
        s_slot[i] = g_list[e * TT + (r < cnt ? r : cnt - 1)];
    }
    __syncthreads();

    uint32_t sb = (smem_u32(dsm) + 127u) & ~127u;

    auto fill = [&](int st, int s) {
        int k0 = kbase + s * BK;
        uint32_t as = sb + st * STAGE;
        uint32_t bs = as + BM * 128;
#pragma unroll
        for (int j = 0; j < 4; j++) {            // A: 128 rows x 8 x 16B
            int idx = tid + j * 256;
            int r = idx >> 3, c = idx & 7;
            size_t arow = (MODE == 0) ? (size_t)(s_slot[r] >> 1) : (size_t)s_slot[r];
            cpa16(as + r * 128 + ((c * 16) ^ ((r & 7) << 4)),
                  Ap + arow * KD + k0 + c * 8);
        }
#pragma unroll
        for (int j = 0; j < 4; j++) {            // B: 128 rows x 8 x 16B
            int idx = tid + j * 256;
            int r = idx >> 3, c = idx & 7;
            cpa16(bs + r * 128 + ((c * 16) ^ ((r & 7) << 4)),
                  Wb + (size_t)(n0 + r) * KD + k0 + c * 8);
        }
    };

    fill(0, 0); cpa_commit();
    fill(1, 1); cpa_commit();

    float acc[2][8][4];
#pragma unroll
    for (int mt = 0; mt < 2; mt++)
#pragma unroll
        for (int nt = 0; nt < 8; nt++)
#pragma unroll
            for (int q = 0; q < 4; q++) acc[mt][nt][q] = 0.0f;

    int a_row = lane & 15;            // row within m16 tile
    int a_kx  = (lane >> 4) << 4;     // 0 or 16 bytes (k8 halves)
    int b_row = lane & 7;             // row within n8 tile
    int b_kx  = (lane >> 3) << 4;     // 0,16,32,48 bytes (4 k8 tiles)

    for (int s = 0; s < NSLAB; s++) {
        cpa_wait1();
        __syncthreads();
        if (s + 2 < NSLAB) fill((s + 2) % 3, s + 2);
        cpa_commit();

        uint32_t ab = sb + (s % 3) * STAGE;
        uint32_t bb = ab + BM * 128;
#pragma unroll
        for (int kh = 0; kh < 2; kh++) {          // k32-halves of the slab
            uint32_t b[8][4];
#pragma unroll
            for (int nt = 0; nt < 8; nt++) {
                int row = wn + nt * 8 + b_row;
                int kb  = kh * 64 + b_kx;
                ldsm4(b[nt], bb + row * 128 + (kb ^ ((row & 7) << 4)));
            }
#pragma unroll
            for (int ks = 0; ks < 2; ks++) {      // k16 steps within the half
                uint32_t a[2][4];
#pragma unroll
                for (int mt = 0; mt < 2; mt++) {
                    int row = wm + mt * 16 + a_row;
                    int kb  = kh * 64 + ks * 32 + a_kx;
                    ldsm4(a[mt], ab + row * 128 + (kb ^ ((row & 7) << 4)));
                }
#pragma unroll
                for (int mt = 0; mt < 2; mt++)
#pragma unroll
                    for (int nt = 0; nt < 8; nt++)
                        mma16(acc[mt][nt], a[mt], b[nt][ks * 2], b[nt][ks * 2 + 1]);
            }
        }
    }

    // ---------------- epilogue ----------------
    int g = lane >> 2, tig = lane & 3;
#pragma unroll
    for (int mt = 0; mt < 2; mt++) {
#pragma unroll
        for (int half = 0; half < 2; half++) {
            int rl = wm + mt * 16 + g + half * 8;
            if (m0 + rl >= cnt) continue;
            int slot = s_slot[rl];
            if (MODE == 0) {
                __half* dst = g_hmid + (size_t)slot * ND;
                const float* bp = bias + (size_t)e * ND;
#pragma unroll
                for (int nt = 0; nt < 8; nt++) {
                    int col = n0 + wn + nt * 8 + 2 * tig;
                    float v0 = acc[mt][nt][half * 2 + 0] + bp[col];
                    float v1 = acc[mt][nt][half * 2 + 1] + bp[col + 1];
                    v0 = 0.5f * v0 * (1.0f + erff(v0 * 0.70710678118654752f));
                    v1 = 0.5f * v1 * (1.0f + erff(v1 * 0.70710678118654752f));
                    *(__half2*)(dst + col) = __floats2half2_rn(v0, v1);
                }
            } else {
                __half* dst = g_y + ((size_t)split * NSLOT + slot) * ND;
#pragma unroll
                for (int nt = 0; nt < 8; nt++) {
                    int col = n0 + wn + nt * 8 + 2 * tig;
                    *(__half2*)(dst + col) = __floats2half2_rn(
                        acc[mt][nt][half * 2 + 0], acc[mt][nt][half * 2 + 1]);
                }
            }
        }
    }
}

// ---------------- launcher ---------------------------------------------------
extern "C" void kernel_launch(void* const* d_in, const int* in_sizes, int n_in,
                              void* d_out, int out_size) {
    const float* x  = (const float*)d_in[0];
    const float* rw = (const float*)d_in[1];
    const float* w1 = (const float*)d_in[2];
    const float* b1 = (const float*)d_in[3];
    const float* w2 = (const float*)d_in[4];
    const float* b2 = (const float*)d_in[5];
    float* out = (float*)d_out;

    void *p_w1h, *p_w2h;
    cudaGetSymbolAddress(&p_w1h, g_w1h);
    cudaGetSymbolAddress(&p_w2h, g_w2h);

    // Two side streams (proven safe). cvt_w1 split into two concurrent halves
    // (one per stream) to raise DRAM occupancy; cvt_w2 follows on s_b under
    // GEMM1's tensor-bound window.
    static cudaStream_t s_a = nullptr, s_b = nullptr;
    static cudaEvent_t ev_root = nullptr, ev_w1a = nullptr, ev_w1b = nullptr,
                       ev_w2 = nullptr;
    if (s_a == nullptr) {
        cudaStreamCreateWithFlags(&s_a, cudaStreamNonBlocking);
        cudaStreamCreateWithFlags(&s_b, cudaStreamNonBlocking);
        cudaEventCreateWithFlags(&ev_root, cudaEventDisableTiming);
        cudaEventCreateWithFlags(&ev_w1a,  cudaEventDisableTiming);
        cudaEventCreateWithFlags(&ev_w1b,  cudaEventDisableTiming);
        cudaEventCreateWithFlags(&ev_w2,   cudaEventDisableTiming);
    }

    const int SMEM = 3 * 32768 + 128;
    cudaFuncSetAttribute(moe_gemm<0, HH, FF, 1>,
                         cudaFuncAttributeMaxDynamicSharedMemorySize, SMEM);
    cudaFuncSetAttribute(moe_gemm<1, FF, HH, NSP2>,
                         cudaFuncAttributeMaxDynamicSharedMemorySize, SMEM);

    const int W1_N8 = EE * FF * HH / 8;         // total 8-float groups in w1
    const int HALF  = W1_N8 / 2;

    // Fork: two concurrent halves of cvt_w1.
    cudaEventRecord(ev_root, 0);
    cudaStreamWaitEvent(s_a, ev_root, 0);
    cudaStreamWaitEvent(s_b, ev_root, 0);
    cvt_half_kernel<<<2368, 256, 0, s_a>>>((const float4*)w1,
                                           (uint4*)p_w1h, HALF);
    cudaEventRecord(ev_w1a, s_a);
    cvt_half_kernel<<<2368, 256, 0, s_b>>>(
        (const float4*)w1 + (size_t)2 * HALF,
        (uint4*)p_w1h + HALF, W1_N8 - HALF);
    cudaEventRecord(ev_w1b, s_b);

    // cvt_w2 chained on s_b after its w1 half; overlaps GEMM1.
    cvt_half_kernel<<<4736, 256, 0, s_b>>>((const float4*)w2, (uint4*)p_w2h,
                                           EE * HH * FF / 8);
    cudaEventRecord(ev_w2, s_b);

    // Main stream: init + router overlap the w1 conversion.
    init_kernel<<<1, 32>>>();
    router_kernel<<<(TT * 32) / 256, 256>>>(x, rw);

    // GEMM1 (monolithic) after router + both w1 halves.
    cudaStreamWaitEvent(0, ev_w1a, 0);
    cudaStreamWaitEvent(0, ev_w1b, 0);
    dim3 g1(FF / 128, TT / 128, EE);
    moe_gemm<0, HH, FF, 1><<<g1, 256, SMEM>>>((const __half*)p_w1h, b1);

    // GEMM2 (monolithic, split-K=2) after GEMM1 + cvt_w2; fp16 partials.
    cudaStreamWaitEvent(0, ev_w2, 0);
    dim3 g2(HH / 128, TT / 128, EE * NSP2);
    moe_gemm<1, FF, HH, NSP2><<<g2, 256, SMEM>>>((const __half*)p_w2h, b2);

    // Combine split-K partials + bias + routing weights into out.
    combine_kernel<<<(TT * HH / 4 + 255) / 256, 256>>>(b2, out);
}